// round 7
// baseline (speedup 1.0000x reference)
#include <cuda_runtime.h>
#include <math.h>

// ---------------------------------------------------------------------------
// TwoTowerRecommender — fp32 FFMA2 towers, 256 threads/block, 8 items/thread
// (acc[16] => ~70 regs => 8 warps/SMSP), transposed-vectorized weights,
// smem aliasing, brand/size precompute.
// Output: user_vec [U,64] then item_vec [T,64] (f32)
// ---------------------------------------------------------------------------

#define MAX_T 100000
#define MAX_U 100000

__device__ float g_text_proj[(size_t)MAX_T * 64];
__device__ float g_hist_pool[(size_t)MAX_U * 64];
__device__ int   g_row_start[MAX_U + 1];
__device__ float g_brand_part[100 * 128];
__device__ float g_size_part[500 * 128];

// Transposed weights, layout [k/4][col][4]: element (k4,c,j) = W[4*k4+j][c].
#define WT_TP 0        // 384x64
#define WT_I1 24576    // 256x128 (rows 0-127, 384-511 of W_i1)
#define WT_I2 57344    // 128x128
#define WT_I3 73728    // 128x64
#define WT_U1 81920    // 192x128
#define WT_U2 106496   // 128x128
#define WT_U3 122880   // 128x64
__device__ float g_wt[131072];

#define DINL __device__ __forceinline__

DINL float2 unpack2f(unsigned long long v) {
    float2 r;
    asm("mov.b64 {%0, %1}, %2;" : "=f"(r.x), "=f"(r.y) : "l"(v));
    return r;
}
DINL void ffma2(unsigned long long& d, unsigned long long a, unsigned long long b) {
    asm("fma.rn.f32x2 %0, %1, %2, %0;" : "+l"(d) : "l"(a), "l"(b));
}

// 2-col accumulate, transposed weights: NI items, cols c and c+64.
#define ACCUM2T(WT, NC, kxoff, KLEN, NI)                                          \
    _Pragma("unroll 2")                                                           \
    for (int k4 = 0; k4 < (KLEN) / 4; k4++) {                                     \
        ulonglong2 w0 = *(const ulonglong2*)((WT) + ((size_t)k4 * (NC) + c) * 4); \
        ulonglong2 w1 = *(const ulonglong2*)((WT) + ((size_t)k4 * (NC) + c + 64) * 4); \
        _Pragma("unroll")                                                         \
        for (int i = 0; i < (NI); i++) {                                          \
            ulonglong2 v = *(const ulonglong2*)(xsb + i * XSTRv + (kxoff) + k4 * 4); \
            ffma2(acc[2*i],   v.x, w0.x); ffma2(acc[2*i],   v.y, w0.y);           \
            ffma2(acc[2*i+1], v.x, w1.x); ffma2(acc[2*i+1], v.y, w1.y);           \
        }                                                                         \
    }

// ---------------------------------------------------------------------------
// Kernel W: weight transpose into g_wt. i1map remaps k>=128 -> k+256.
// ---------------------------------------------------------------------------
__global__ void k_wt(const float* __restrict__ src, int dst_off, int K, int N, int i1map)
{
    int idx = blockIdx.x * blockDim.x + threadIdx.x;
    if (idx >= K * N) return;
    int k = idx / N, c = idx % N;
    int srcrow = (i1map && k >= 128) ? k + 256 : k;
    g_wt[dst_off + ((size_t)(k >> 2) * N + c) * 4 + (k & 3)] = src[(size_t)srcrow * N + c];
}

// ---------------------------------------------------------------------------
// Kernel 0: precompute brand/size contributions to item layer 1.
// ---------------------------------------------------------------------------
__global__ void __launch_bounds__(128) k_pre(
    const float* __restrict__ hb, const float* __restrict__ hz,
    const float* __restrict__ W1, int n_brand, int n_size)
{
    __shared__ float row[128];
    const int t = threadIdx.x;
    const int r = blockIdx.x;
    const float* src;
    const float* W;
    float* dst;
    if (r < n_brand) {
        src = hb + (size_t)r * 128; W = W1 + (size_t)128 * 128; dst = g_brand_part + (size_t)r * 128;
    } else {
        int rr = r - n_brand;
        src = hz + (size_t)rr * 128; W = W1 + (size_t)256 * 128; dst = g_size_part + (size_t)rr * 128;
    }
    row[t] = src[t];
    __syncthreads();
    float a = 0.0f;
#pragma unroll 4
    for (int k = 0; k < 128; k++) a = fmaf(row[k], W[(size_t)k * 128 + t], a);
    dst[t] = a;
}

// ---------------------------------------------------------------------------
// Kernel 1: text projection  relu(text_emb @ W_tp + b_tp) -> g_text_proj
// 256 threads, 32 items; c = t&63, item group (t>>6)*8, acc[8].
// ---------------------------------------------------------------------------
#define TXT_STR 392
#define TXT_SMEM (32 * TXT_STR * 4)

__global__ void __launch_bounds__(256) k_text(
    const float* __restrict__ text, const float* __restrict__ btp, int n)
{
    extern __shared__ float smT[];
    float* xs = smT;
    const int t  = threadIdx.x;
    const int i0 = blockIdx.x * 32;

    for (int idx = t; idx < 32 * 96; idx += 256) {
        int i = idx / 96, q = idx % 96, k = q * 4;
        int item = i0 + i; if (item >= n) item = n - 1;
        *(float4*)(xs + i * TXT_STR + k) = *(const float4*)(text + (size_t)item * 384 + k);
    }
    __syncthreads();

    const int c  = t & 63;
    const int ib = (t >> 6) * 8;
    const float* wt = g_wt + WT_TP;
    unsigned long long acc[8];
#pragma unroll
    for (int i = 0; i < 8; i++) acc[i] = 0ull;

#pragma unroll 2
    for (int k4 = 0; k4 < 96; k4++) {
        ulonglong2 w = *(const ulonglong2*)(wt + ((size_t)k4 * 64 + c) * 4);
#pragma unroll
        for (int i = 0; i < 8; i++) {
            ulonglong2 v = *(const ulonglong2*)(xs + (ib + i) * TXT_STR + k4 * 4);
            ffma2(acc[i], v.x, w.x);
            ffma2(acc[i], v.y, w.y);
        }
    }
    float b = btp[c];
#pragma unroll
    for (int i = 0; i < 8; i++) {
        float2 p = unpack2f(acc[i]);
        float r = fmaxf(p.x + p.y + b, 0.0f);
        int item = i0 + ib + i;
        if (item < n) g_text_proj[(size_t)item * 64 + c] = r;
    }
}

// ---------------------------------------------------------------------------
// Kernel 2: item tower.  x[256] = [h_tire | specs | tproj]
// 256 threads, 32 items, 8 items/thread, cols {c, c+64}.
// ---------------------------------------------------------------------------
#define IT_XSTR 264
#define IT_HSTR 132
#define IT_OSTR 68
#define ITEM_SMEM ((8448 + 4224) * 4 + 64 * 4)

__global__ void __launch_bounds__(256) k_item(
    const float* __restrict__ ht, const float* __restrict__ sp,
    const int* __restrict__ bidx, const int* __restrict__ sidx,
    const float* __restrict__ b1, const float* __restrict__ b2,
    const float* __restrict__ b3,
    float* __restrict__ out_item, int n)
{
    extern __shared__ float smI[];
    float* xs   = smI;                    // [32][264]
    float* h1s  = smI + 8448;             // [32][132]
    float* h2s  = xs;                     // alias (xs dead after layer1)
    float* outs = h1s;                    // alias (h1 dead after layer2), stride 68
    float* scl  = h1s + 32 * IT_OSTR;
    int*   sbv  = (int*)(smI + 8448 + 4224);
    int*   ssv  = sbv + 32;

    const int t  = threadIdx.x;
    const int i0 = blockIdx.x * 32;

    if (t < 32) {
        int item = i0 + t; if (item >= n) item = n - 1;
        sbv[t] = bidx[item];
        ssv[t] = sidx[item];
    }

    for (int idx = t; idx < 32 * 64; idx += 256) {
        int i = idx >> 6, q = idx & 63, k = q * 4;
        int item = i0 + i; if (item >= n) item = n - 1;
        const float* src;
        if      (k < 128) src = ht + (size_t)item * 128 + k;
        else if (k < 192) src = sp + (size_t)item * 64 + (k - 128);
        else              src = g_text_proj + (size_t)item * 64 + (k - 192);
        *(float4*)(xs + i * IT_XSTR + k) = *(const float4*)src;
    }
    __syncthreads();

    const int c = t & 63;
    const int g = (t >> 6) * 8;

    // ---- layer 1: 256 -> 128 relu, + brand/size parts
    {
        const float* xsb = xs + g * IT_XSTR;
        const int XSTRv = IT_XSTR;
        unsigned long long acc[16];
#pragma unroll
        for (int i = 0; i < 16; i++) acc[i] = 0ull;
        ACCUM2T(g_wt + WT_I1, 128, 0, 256, 8);
        float bb0 = b1[c], bb1 = b1[c + 64];
#pragma unroll
        for (int i = 0; i < 8; i++) {
            const float* bp  = g_brand_part + (size_t)sbv[g + i] * 128;
            const float* zp  = g_size_part  + (size_t)ssv[g + i] * 128;
            float2 p0 = unpack2f(acc[2 * i]);
            float2 p1 = unpack2f(acc[2 * i + 1]);
            h1s[(g + i) * IT_HSTR + c]      = fmaxf(p0.x + p0.y + bb0 + bp[c]      + zp[c],      0.0f);
            h1s[(g + i) * IT_HSTR + c + 64] = fmaxf(p1.x + p1.y + bb1 + bp[c + 64] + zp[c + 64], 0.0f);
        }
    }
    __syncthreads();

    // ---- layer 2: 128 -> 128 relu (writes over xs region)
    {
        const float* xsb = h1s + g * IT_HSTR;
        const int XSTRv = IT_HSTR;
        unsigned long long acc[16];
#pragma unroll
        for (int i = 0; i < 16; i++) acc[i] = 0ull;
        ACCUM2T(g_wt + WT_I2, 128, 0, 128, 8);
        float bb0 = b2[c], bb1 = b2[c + 64];
#pragma unroll
        for (int i = 0; i < 8; i++) {
            float2 p0 = unpack2f(acc[2 * i]);
            float2 p1 = unpack2f(acc[2 * i + 1]);
            h2s[(g + i) * IT_HSTR + c]      = fmaxf(p0.x + p0.y + bb0, 0.0f);
            h2s[(g + i) * IT_HSTR + c + 64] = fmaxf(p1.x + p1.y + bb1, 0.0f);
        }
    }
    __syncthreads();

    // ---- layer 3: 128 -> 64 (writes over h1 region)
    {
        const float* wt = g_wt + WT_I3;
        unsigned long long acc[8];
#pragma unroll
        for (int i = 0; i < 8; i++) acc[i] = 0ull;
#pragma unroll 2
        for (int k4 = 0; k4 < 32; k4++) {
            ulonglong2 w = *(const ulonglong2*)(wt + ((size_t)k4 * 64 + c) * 4);
#pragma unroll
            for (int i = 0; i < 8; i++) {
                ulonglong2 v = *(const ulonglong2*)(h2s + (g + i) * IT_HSTR + k4 * 4);
                ffma2(acc[i], v.x, w.x);
                ffma2(acc[i], v.y, w.y);
            }
        }
        float b = b3[c];
#pragma unroll
        for (int i = 0; i < 8; i++) {
            float2 p = unpack2f(acc[i]);
            outs[(g + i) * IT_OSTR + c] = p.x + p.y + b;
        }
    }
    __syncthreads();

    if (t < 32) {
        float s = 0.0f;
#pragma unroll
        for (int q = 0; q < 16; q++) {
            float4 v = *(const float4*)(outs + t * IT_OSTR + q * 4);
            s += v.x * v.x + v.y * v.y + v.z * v.z + v.w * v.w;
        }
        scl[t] = 1.0f / fmaxf(sqrtf(s), 1e-12f);
    }
    __syncthreads();

    for (int idx = t; idx < 32 * 64; idx += 256) {
        int i = idx >> 6, cc = idx & 63;
        int item = i0 + i;
        if (item < n) out_item[(size_t)item * 64 + cc] = outs[i * IT_OSTR + cc] * scl[i];
    }
}

// ---------------------------------------------------------------------------
// Kernel 3: row starts from sorted hist_segments
// ---------------------------------------------------------------------------
__global__ void k_rowstart(const int* __restrict__ seg, int E, int n_users)
{
    int e = blockIdx.x * blockDim.x + threadIdx.x;
    if (e >= E) return;
    int s = seg[e];
    int p = (e == 0) ? -1 : seg[e - 1];
    for (int u = p + 1; u <= s; ++u) g_row_start[u] = e;
    if (e == E - 1) {
        for (int u = s + 1; u <= n_users; ++u) g_row_start[u] = E;
    }
}

// ---------------------------------------------------------------------------
// Kernel 4: history mean-pool. One warp per user, 2 dims per lane.
// (At L2-bandwidth roofline; unchanged.)
// ---------------------------------------------------------------------------
__global__ void k_hist(const float* __restrict__ item_vec,
                       const int* __restrict__ items, int n_users)
{
    int gw   = (blockIdx.x * blockDim.x + threadIdx.x) >> 5;
    int lane = threadIdx.x & 31;
    if (gw >= n_users) return;
    int s = g_row_start[gw], e = g_row_start[gw + 1];
    float a0 = 0.0f, a1 = 0.0f;
    if (e > s) {
        int it = items[s];
        for (int j = s; j < e; ++j) {
            int nx = (j + 1 < e) ? items[j + 1] : 0;
            const float* p = item_vec + (size_t)it * 64;
            a0 += p[lane];
            a1 += p[32 + lane];
            it = nx;
        }
        float inv = 1.0f / (float)(e - s);
        a0 *= inv; a1 *= inv;
    }
    g_hist_pool[(size_t)gw * 64 + lane]      = a0;
    g_hist_pool[(size_t)gw * 64 + 32 + lane] = a1;
}

// ---------------------------------------------------------------------------
// Kernel 5: user tower. x[192] = [h_user | hist_pool], 256 threads.
// ---------------------------------------------------------------------------
#define US_XSTR 200
#define USER_SMEM ((6400 + 4224) * 4)

__global__ void __launch_bounds__(256) k_user(
    const float* __restrict__ hu,
    const float* __restrict__ b1, const float* __restrict__ b2,
    const float* __restrict__ b3,
    float* __restrict__ out_user, int n)
{
    extern __shared__ float smU[];
    float* xs   = smU;                    // [32][200]
    float* h1s  = smU + 6400;             // [32][132]
    float* h2s  = xs;                     // alias
    float* outs = h1s;                    // alias, stride 68
    float* scl  = h1s + 32 * IT_OSTR;

    const int t  = threadIdx.x;
    const int i0 = blockIdx.x * 32;

    for (int idx = t; idx < 32 * 48; idx += 256) {
        int i = idx / 48, q = idx % 48, k = q * 4;
        int u = i0 + i; if (u >= n) u = n - 1;
        const float* src = (k < 128) ? (hu + (size_t)u * 128 + k)
                                     : (g_hist_pool + (size_t)u * 64 + (k - 128));
        *(float4*)(xs + i * US_XSTR + k) = *(const float4*)src;
    }
    __syncthreads();

    const int c = t & 63;
    const int g = (t >> 6) * 8;

    // layer 1: 192 -> 128 relu
    {
        const float* xsb = xs + g * US_XSTR;
        const int XSTRv = US_XSTR;
        unsigned long long acc[16];
#pragma unroll
        for (int i = 0; i < 16; i++) acc[i] = 0ull;
        ACCUM2T(g_wt + WT_U1, 128, 0, 192, 8);
        float bb0 = b1[c], bb1 = b1[c + 64];
#pragma unroll
        for (int i = 0; i < 8; i++) {
            float2 p0 = unpack2f(acc[2 * i]);
            float2 p1 = unpack2f(acc[2 * i + 1]);
            h1s[(g + i) * IT_HSTR + c]      = fmaxf(p0.x + p0.y + bb0, 0.0f);
            h1s[(g + i) * IT_HSTR + c + 64] = fmaxf(p1.x + p1.y + bb1, 0.0f);
        }
    }
    __syncthreads();

    // layer 2: 128 -> 128 relu (writes over xs region)
    {
        const float* xsb = h1s + g * IT_HSTR;
        const int XSTRv = IT_HSTR;
        unsigned long long acc[16];
#pragma unroll
        for (int i = 0; i < 16; i++) acc[i] = 0ull;
        ACCUM2T(g_wt + WT_U2, 128, 0, 128, 8);
        float bb0 = b2[c], bb1 = b2[c + 64];
#pragma unroll
        for (int i = 0; i < 8; i++) {
            float2 p0 = unpack2f(acc[2 * i]);
            float2 p1 = unpack2f(acc[2 * i + 1]);
            h2s[(g + i) * IT_HSTR + c]      = fmaxf(p0.x + p0.y + bb0, 0.0f);
            h2s[(g + i) * IT_HSTR + c + 64] = fmaxf(p1.x + p1.y + bb1, 0.0f);
        }
    }
    __syncthreads();

    // layer 3: 128 -> 64 (writes over h1 region)
    {
        const float* wt = g_wt + WT_U3;
        unsigned long long acc[8];
#pragma unroll
        for (int i = 0; i < 8; i++) acc[i] = 0ull;
#pragma unroll 2
        for (int k4 = 0; k4 < 32; k4++) {
            ulonglong2 w = *(const ulonglong2*)(wt + ((size_t)k4 * 64 + c) * 4);
#pragma unroll
            for (int i = 0; i < 8; i++) {
                ulonglong2 v = *(const ulonglong2*)(h2s + (g + i) * IT_HSTR + k4 * 4);
                ffma2(acc[i], v.x, w.x);
                ffma2(acc[i], v.y, w.y);
            }
        }
        float b = b3[c];
#pragma unroll
        for (int i = 0; i < 8; i++) {
            float2 p = unpack2f(acc[i]);
            outs[(g + i) * IT_OSTR + c] = p.x + p.y + b;
        }
    }
    __syncthreads();

    if (t < 32) {
        float s = 0.0f;
#pragma unroll
        for (int q = 0; q < 16; q++) {
            float4 v = *(const float4*)(outs + t * IT_OSTR + q * 4);
            s += v.x * v.x + v.y * v.y + v.z * v.z + v.w * v.w;
        }
        scl[t] = 1.0f / fmaxf(sqrtf(s), 1e-12f);
    }
    __syncthreads();

    for (int idx = t; idx < 32 * 64; idx += 256) {
        int i = idx >> 6, cc = idx & 63;
        int u = i0 + i;
        if (u < n) out_user[(size_t)u * 64 + cc] = outs[i * IT_OSTR + cc] * scl[i];
    }
}

// ---------------------------------------------------------------------------
extern "C" void kernel_launch(void* const* d_in, const int* in_sizes, int n_in,
                              void* d_out, int out_size)
{
    const float* h_user   = (const float*)d_in[0];
    const float* h_tire   = (const float*)d_in[1];
    const float* h_brand  = (const float*)d_in[2];
    const float* h_size   = (const float*)d_in[3];
    const float* specs    = (const float*)d_in[4];
    const float* text_emb = (const float*)d_in[5];
    const int*   bidx     = (const int*)d_in[6];
    const int*   sidx     = (const int*)d_in[7];
    const int*   hitems   = (const int*)d_in[8];
    const int*   hseg     = (const int*)d_in[9];
    const float* W_tp = (const float*)d_in[10]; const float* b_tp = (const float*)d_in[11];
    const float* W_i1 = (const float*)d_in[12]; const float* b_i1 = (const float*)d_in[13];
    const float* W_i2 = (const float*)d_in[14]; const float* b_i2 = (const float*)d_in[15];
    const float* W_i3 = (const float*)d_in[16]; const float* b_i3 = (const float*)d_in[17];
    const float* W_u1 = (const float*)d_in[18]; const float* b_u1 = (const float*)d_in[19];
    const float* W_u2 = (const float*)d_in[20]; const float* b_u2 = (const float*)d_in[21];
    const float* W_u3 = (const float*)d_in[22]; const float* b_u3 = (const float*)d_in[23];

    const int n_users = in_sizes[0] / 128;
    const int n_tires = in_sizes[1] / 128;
    const int n_brand = in_sizes[2] / 128;
    const int n_size  = in_sizes[3] / 128;
    const int E       = in_sizes[8];

    float* out      = (float*)d_out;
    float* user_vec = out;
    float* item_vec = out + (size_t)n_users * 64;

    cudaFuncSetAttribute(k_text, cudaFuncAttributeMaxDynamicSharedMemorySize, TXT_SMEM);
    cudaFuncSetAttribute(k_item, cudaFuncAttributeMaxDynamicSharedMemorySize, ITEM_SMEM);
    cudaFuncSetAttribute(k_user, cudaFuncAttributeMaxDynamicSharedMemorySize, USER_SMEM);

    const int itemBlocks = (n_tires + 31) / 32;
    const int userBlocks = (n_users + 31) / 32;

    // weight transposes (tiny; ordered before consumers on the stream)
    k_wt<<<(384 * 64  + 255) / 256, 256>>>(W_tp, WT_TP, 384, 64,  0);
    k_wt<<<(256 * 128 + 255) / 256, 256>>>(W_i1, WT_I1, 256, 128, 1);
    k_wt<<<(128 * 128 + 255) / 256, 256>>>(W_i2, WT_I2, 128, 128, 0);
    k_wt<<<(128 * 64  + 255) / 256, 256>>>(W_i3, WT_I3, 128, 64,  0);
    k_wt<<<(192 * 128 + 255) / 256, 256>>>(W_u1, WT_U1, 192, 128, 0);
    k_wt<<<(128 * 128 + 255) / 256, 256>>>(W_u2, WT_U2, 128, 128, 0);
    k_wt<<<(128 * 64  + 255) / 256, 256>>>(W_u3, WT_U3, 128, 64,  0);

    k_pre<<<n_brand + n_size, 128>>>(h_brand, h_size, W_i1, n_brand, n_size);

    k_text<<<itemBlocks, 256, TXT_SMEM>>>(text_emb, b_tp, n_tires);

    k_item<<<itemBlocks, 256, ITEM_SMEM>>>(h_tire, specs, bidx, sidx,
                                           b_i1, b_i2, b_i3,
                                           item_vec, n_tires);

    k_rowstart<<<(E + 255) / 256, 256>>>(hseg, E, n_users);

    k_hist<<<((size_t)n_users * 32 + 255) / 256, 256>>>(item_vec, hitems, n_users);

    k_user<<<userBlocks, 256, USER_SMEM>>>(h_user,
                                           b_u1, b_u2, b_u3,
                                           user_vec, n_users);
}

// round 15
// speedup vs baseline: 1.4562x; 1.4562x over previous
#include <cuda_runtime.h>
#include <cuda_bf16.h>
#include <math.h>
#include <cstdint>
#include <cstring>

// ---------------------------------------------------------------------------
// TwoTowerRecommender — split-bf16 mma.sync (m16n8k16), 3-pass hi/lo, fp32
// named-register accumulators. Interlayer activations are f32 device globals;
// hi/lo bf16 split happens during smem staging. No cudaGetSymbolAddress, no
// giant bf16 blobs (statics ~155MB, near the proven R5 regime).
// Output: user_vec [U,64] then item_vec [T,64] (f32)
// ---------------------------------------------------------------------------

#define MAX_U 100000
#define ROWSPAD 100032          // ceil(100000/64)*64

__device__ float g_hist_pool[(size_t)MAX_U * 64];
__device__ int   g_row_start[MAX_U + 1];
__device__ float g_brand_part[100 * 128];
__device__ float g_size_part[500 * 128];

// f32 interlayer activations.
__device__ __align__(16) float g_tproj[(size_t)ROWSPAD * 64];   // 25.6MB
__device__ __align__(16) float g_h1[(size_t)ROWSPAD * 128];     // 51.2MB
__device__ __align__(16) float g_h2[(size_t)ROWSPAD * 128];     // 51.2MB

// Weight blobs: [split][n][K] bf16 (transposed). Offsets in elements.
#define WB_TP 0        // N=64  K=384 : 49152
#define WB_I1 49152    // N=128 K=256 : 65536
#define WB_I2 114688   // N=128 K=128 : 32768
#define WB_I3 147456   // N=64  K=128 : 16384
#define WB_U1 163840   // N=128 K=192 : 49152
#define WB_U2 212992   // N=128 K=128 : 32768
#define WB_U3 245760   // N=64  K=128 : 16384
__device__ __align__(16) __nv_bfloat16 g_wb[262144];

#define DINL __device__ __forceinline__

DINL __nv_bfloat16 bhi(float v) { return __float2bfloat16(v); }
DINL __nv_bfloat16 blo(float v, __nv_bfloat16 h) {
    return __float2bfloat16(v - __bfloat162float(h));
}
DINL uint32_t pk2(__nv_bfloat16 a, __nv_bfloat16 b) {
    uint32_t r;
    __nv_bfloat162 t;
    t.x = a; t.y = b;
    memcpy(&r, &t, 4);
    return r;
}

// Device-global selector (host never takes symbol addresses).
DINL const float* src_sel(int sel, const float* p) {
    if (sel == 1) return g_h1;
    if (sel == 2) return g_h2;
    if (sel == 3) return g_tproj;
    if (sel == 4) return g_hist_pool;
    return p;
}
DINL float* dst_sel(int sel) {
    if (sel == 1) return g_h1;
    if (sel == 2) return g_h2;
    return g_tproj;   // 3
}

// MMA as a macro on direct member lvalues — no address-taking.
#define MMA4(D, A0, A1, A2, A3, B0, B1)                                   \
    asm volatile(                                                         \
        "mma.sync.aligned.m16n8k16.row.col.f32.bf16.bf16.f32 "            \
        "{%0,%1,%2,%3}, {%4,%5,%6,%7}, {%8,%9}, {%0,%1,%2,%3};\n"         \
        : "+f"((D).x), "+f"((D).y), "+f"((D).z), "+f"((D).w)              \
        : "r"(A0), "r"(A1), "r"(A2), "r"(A3), "r"(B0), "r"(B1))

#define FORN8(E)  E(0) E(1) E(2) E(3) E(4) E(5) E(6) E(7)
#define FORN16(E) FORN8(E) E(8) E(9) E(10) E(11) E(12) E(13) E(14) E(15)

// ---------------------------------------------------------------------------
// Weight split+transpose into g_wb:  blob[split][n][K] = split_bf16(W[k][n]).
// remap: item L1 uses orig rows {0..127, 384..511}.
// ---------------------------------------------------------------------------
__global__ void k_wsplit(const float* __restrict__ src, int off,
                         int K, int N, int remap)
{
    int idx = blockIdx.x * blockDim.x + threadIdx.x;
    if (idx >= K * N) return;
    int k = idx / N, n = idx % N;
    int sr = (remap && k >= 128) ? k + 256 : k;
    float v = src[(size_t)sr * N + n];
    __nv_bfloat16 h = bhi(v), l = blo(v, h);
    g_wb[off + (size_t)n * K + k] = h;
    g_wb[off + ((size_t)N + n) * K + k] = l;
}

// ---------------------------------------------------------------------------
// Split-bf16 MMA GEMM:  D[64,N] per block = A[64,K] @ Wt[N,K]^T.
// A is staged from f32 sources (up to 3, chunk-granular) and split to hi/lo
// bf16 in smem. mode 0: relu(D+bias(+parts)) -> f32 dst global.
// mode 1: l2norm(D+bias) -> f32 outp (N==64).
// ---------------------------------------------------------------------------
#define AST 72

template<int N, int K>
__global__ void __launch_bounds__(128) k_gemm(
    const float* srcA, int sA, int chA, int selA,
    const float* srcB, int sB, int chB, int selB,
    const float* srcC, int sC, int selC,
    int wbOff,
    const float* __restrict__ bias, int mode,
    int dstSel, int dstStride,
    int useParts, const int* __restrict__ bidx, const int* __restrict__ sidx,
    float* __restrict__ outp, int nrows)
{
    constexpr int NCH = K / 64;
    constexpr int NT  = N / 8;
    extern __shared__ __nv_bfloat16 sm[];
    __nv_bfloat16* const as = sm;                 // [2][64][AST]
    __nv_bfloat16* const bs = sm + 2 * 64 * AST;  // [2][N][AST]

    const int t = threadIdx.x, wid = t >> 5, lane = t & 31;
    const int g = lane >> 2, q = lane & 3;
    const int blk = blockIdx.x;
    const int rb = wid * 16;

    const float* pA = src_sel(selA, srcA);
    const float* pB = src_sel(selB, srcB);
    const float* pC = src_sel(selC, srcC);

    float4 d0  = make_float4(0.f, 0.f, 0.f, 0.f), d1 = d0,  d2 = d0,  d3 = d0;
    float4 d4  = d0, d5 = d0, d6 = d0, d7 = d0;
    float4 d8  = d0, d9 = d0, d10 = d0, d11 = d0;
    float4 d12 = d0, d13 = d0, d14 = d0, d15 = d0;

    for (int ch = 0; ch < NCH; ch++) {
        __syncthreads();
        // select f32 source for this 64-col chunk
        const float* csrc;
        int cstride, coff;
        if (ch < chA)            { csrc = pA; cstride = sA; coff = ch * 64; }
        else if (ch < chA + chB) { csrc = pB; cstride = sB; coff = (ch - chA) * 64; }
        else                     { csrc = pC; cstride = sC; coff = (ch - chA - chB) * 64; }

        // stage A: 64 rows x 64 f32 -> split hi/lo bf16 in smem
        for (int i = t; i < 1024; i += 128) {
            int r = i >> 4, u = i & 15;
            int sr = blk * 64 + r;
            if (sr >= nrows) sr = nrows - 1;
            float4 v = *(const float4*)(csrc + (size_t)sr * cstride + coff + u * 4);
            __nv_bfloat16 h0 = bhi(v.x), l0 = blo(v.x, h0);
            __nv_bfloat16 h1 = bhi(v.y), l1 = blo(v.y, h1);
            __nv_bfloat16 h2 = bhi(v.z), l2 = blo(v.z, h2);
            __nv_bfloat16 h3 = bhi(v.w), l3 = blo(v.w, h3);
            *(uint32_t*)(as + r * AST + u * 4)            = pk2(h0, h1);
            *(uint32_t*)(as + r * AST + u * 4 + 2)        = pk2(h2, h3);
            *(uint32_t*)(as + 64 * AST + r * AST + u * 4)     = pk2(l0, l1);
            *(uint32_t*)(as + 64 * AST + r * AST + u * 4 + 2) = pk2(l2, l3);
        }
        // stage B: 2 splits x N rows x 64 k (4-bf16 units) from g_wb
        for (int i = t; i < 2 * N * 16; i += 128) {
            int sp = i / (N * 16);
            int rem = i - sp * N * 16;
            int r = rem >> 4, u = rem & 15;
            *(unsigned long long*)(bs + sp * N * AST + r * AST + u * 4) =
                *(const unsigned long long*)(g_wb + wbOff + ((size_t)sp * N + r) * K + ch * 64 + u * 4);
        }
        __syncthreads();

#pragma unroll
        for (int kk = 0; kk < 4; kk++) {
            const int k0 = kk * 16 + q * 2;
            const int r0 = rb + g, r1 = rb + g + 8;
            const __nv_bfloat16* asl = as + 64 * AST;
            uint32_t ah0 = *(const uint32_t*)(as  + r0 * AST + k0);
            uint32_t ah1 = *(const uint32_t*)(as  + r1 * AST + k0);
            uint32_t ah2 = *(const uint32_t*)(as  + r0 * AST + k0 + 8);
            uint32_t ah3 = *(const uint32_t*)(as  + r1 * AST + k0 + 8);
            uint32_t al0 = *(const uint32_t*)(asl + r0 * AST + k0);
            uint32_t al1 = *(const uint32_t*)(asl + r1 * AST + k0);
            uint32_t al2 = *(const uint32_t*)(asl + r0 * AST + k0 + 8);
            uint32_t al3 = *(const uint32_t*)(asl + r1 * AST + k0 + 8);

#define MMA_STEP(i) {                                                          \
            const __nv_bfloat16* bp_ = bs + ((i) * 8 + g) * AST;               \
            uint32_t bh0 = *(const uint32_t*)(bp_ + k0);                       \
            uint32_t bh1 = *(const uint32_t*)(bp_ + k0 + 8);                   \
            uint32_t bl0 = *(const uint32_t*)(bp_ + N * AST + k0);             \
            uint32_t bl1 = *(const uint32_t*)(bp_ + N * AST + k0 + 8);         \
            MMA4(d##i, ah0, ah1, ah2, ah3, bh0, bh1);                          \
            MMA4(d##i, ah0, ah1, ah2, ah3, bl0, bl1);                          \
            MMA4(d##i, al0, al1, al2, al3, bh0, bh1);                          \
        }
            if constexpr (NT == 8) { FORN8(MMA_STEP) }
            else                   { FORN16(MMA_STEP) }
#undef MMA_STEP
        }
    }

    // ---- epilogue ----
    const int grow0 = blk * 64 + rb + g;
    const int grow1 = grow0 + 8;

    if (mode == 1) {
        float ss0 = 0.0f, ss1 = 0.0f;
#define EPI_N(i) {                                                             \
        int c0 = (i) * 8 + q * 2;                                              \
        float b0 = bias[c0], b1 = bias[c0 + 1];                                \
        d##i.x += b0; d##i.y += b1; d##i.z += b0; d##i.w += b1;                \
        ss0 += d##i.x * d##i.x + d##i.y * d##i.y;                              \
        ss1 += d##i.z * d##i.z + d##i.w * d##i.w; }
        FORN8(EPI_N)
#undef EPI_N
        ss0 += __shfl_xor_sync(0xFFFFFFFFu, ss0, 1);
        ss0 += __shfl_xor_sync(0xFFFFFFFFu, ss0, 2);
        ss1 += __shfl_xor_sync(0xFFFFFFFFu, ss1, 1);
        ss1 += __shfl_xor_sync(0xFFFFFFFFu, ss1, 2);
        float inv0 = 1.0f / fmaxf(sqrtf(ss0), 1e-12f);
        float inv1 = 1.0f / fmaxf(sqrtf(ss1), 1e-12f);
#define EPI_NS(i) {                                                            \
        if (grow0 < nrows)                                                     \
            *(float2*)(outp + (size_t)grow0 * 64 + (i) * 8 + q * 2) =          \
                make_float2(d##i.x * inv0, d##i.y * inv0);                     \
        if (grow1 < nrows)                                                     \
            *(float2*)(outp + (size_t)grow1 * 64 + (i) * 8 + q * 2) =          \
                make_float2(d##i.z * inv1, d##i.w * inv1); }
        FORN8(EPI_NS)
#undef EPI_NS
    } else {
        float* dst = dst_sel(dstSel);
        const float *bp0 = g_brand_part, *zp0 = g_size_part;
        const float *bp1 = g_brand_part, *zp1 = g_size_part;
        if (useParts) {
            int rr0 = grow0 < nrows ? grow0 : nrows - 1;
            int rr1 = grow1 < nrows ? grow1 : nrows - 1;
            bp0 = g_brand_part + (size_t)bidx[rr0] * 128;
            zp0 = g_size_part  + (size_t)sidx[rr0] * 128;
            bp1 = g_brand_part + (size_t)bidx[rr1] * 128;
            zp1 = g_size_part  + (size_t)sidx[rr1] * 128;
        }
        float* dr0 = dst + (size_t)grow0 * dstStride;
        float* dr1 = dst + (size_t)grow1 * dstStride;
#define EPI_B(i) {                                                             \
        int c0 = (i) * 8 + q * 2;                                              \
        float b0 = bias[c0], b1 = bias[c0 + 1];                                \
        float v00 = d##i.x + b0, v01 = d##i.y + b1;                            \
        float v10 = d##i.z + b0, v11 = d##i.w + b1;                            \
        if (useParts) {                                                        \
            v00 += bp0[c0] + zp0[c0];     v01 += bp0[c0 + 1] + zp0[c0 + 1];    \
            v10 += bp1[c0] + zp1[c0];     v11 += bp1[c0 + 1] + zp1[c0 + 1];    \
        }                                                                      \
        if (grow0 < nrows)                                                     \
            *(float2*)(dr0 + c0) = make_float2(fmaxf(v00, 0.f), fmaxf(v01, 0.f)); \
        if (grow1 < nrows)                                                     \
            *(float2*)(dr1 + c0) = make_float2(fmaxf(v10, 0.f), fmaxf(v11, 0.f)); }
        if constexpr (NT == 8) { FORN8(EPI_B) }
        else                   { FORN16(EPI_B) }
#undef EPI_B
    }
}

// ---------------------------------------------------------------------------
// k_pre: brand/size f32 contributions to item layer 1.
// ---------------------------------------------------------------------------
__global__ void __launch_bounds__(128) k_pre(
    const float* __restrict__ hb, const float* __restrict__ hz,
    const float* __restrict__ W1, int n_brand, int n_size)
{
    __shared__ float rowv[128];
    const int t = threadIdx.x;
    const int r = blockIdx.x;
    const float* src;
    const float* W;
    float* dst;
    if (r < n_brand) {
        src = hb + (size_t)r * 128; W = W1 + (size_t)128 * 128; dst = g_brand_part + (size_t)r * 128;
    } else {
        int rr = r - n_brand;
        src = hz + (size_t)rr * 128; W = W1 + (size_t)256 * 128; dst = g_size_part + (size_t)rr * 128;
    }
    rowv[t] = src[t];
    __syncthreads();
    float a = 0.0f;
#pragma unroll 4
    for (int k = 0; k < 128; k++) a = fmaf(rowv[k], W[(size_t)k * 128 + t], a);
    dst[t] = a;
}

// ---------------------------------------------------------------------------
// k_rowstart + k_hist (at rooflines; unchanged).
// ---------------------------------------------------------------------------
__global__ void k_rowstart(const int* __restrict__ seg, int E, int n_users)
{
    int e = blockIdx.x * blockDim.x + threadIdx.x;
    if (e >= E) return;
    int s = seg[e];
    int p = (e == 0) ? -1 : seg[e - 1];
    for (int u = p + 1; u <= s; ++u) g_row_start[u] = e;
    if (e == E - 1) {
        for (int u = s + 1; u <= n_users; ++u) g_row_start[u] = E;
    }
}

__global__ void k_hist(const float* __restrict__ item_vec,
                       const int* __restrict__ items, int n_users)
{
    int gw   = (blockIdx.x * blockDim.x + threadIdx.x) >> 5;
    int lane = threadIdx.x & 31;
    if (gw >= n_users) return;
    int s = g_row_start[gw], e = g_row_start[gw + 1];
    float a0 = 0.0f, a1 = 0.0f;
    if (e > s) {
        int it = items[s];
        for (int j = s; j < e; ++j) {
            int nx = (j + 1 < e) ? items[j + 1] : 0;
            const float* p = item_vec + (size_t)it * 64;
            a0 += p[lane];
            a1 += p[32 + lane];
            it = nx;
        }
        float inv = 1.0f / (float)(e - s);
        a0 *= inv; a1 *= inv;
    }
    g_hist_pool[(size_t)gw * 64 + lane]      = a0;
    g_hist_pool[(size_t)gw * 64 + 32 + lane] = a1;
}

// ---------------------------------------------------------------------------
extern "C" void kernel_launch(void* const* d_in, const int* in_sizes, int n_in,
                              void* d_out, int out_size)
{
    const float* h_user   = (const float*)d_in[0];
    const float* h_tire   = (const float*)d_in[1];
    const float* h_brand  = (const float*)d_in[2];
    const float* h_size   = (const float*)d_in[3];
    const float* specs    = (const float*)d_in[4];
    const float* text_emb = (const float*)d_in[5];
    const int*   bidx     = (const int*)d_in[6];
    const int*   sidx     = (const int*)d_in[7];
    const int*   hitems   = (const int*)d_in[8];
    const int*   hseg     = (const int*)d_in[9];
    const float* W_tp = (const float*)d_in[10]; const float* b_tp = (const float*)d_in[11];
    const float* W_i1 = (const float*)d_in[12]; const float* b_i1 = (const float*)d_in[13];
    const float* W_i2 = (const float*)d_in[14]; const float* b_i2 = (const float*)d_in[15];
    const float* W_i3 = (const float*)d_in[16]; const float* b_i3 = (const float*)d_in[17];
    const float* W_u1 = (const float*)d_in[18]; const float* b_u1 = (const float*)d_in[19];
    const float* W_u2 = (const float*)d_in[20]; const float* b_u2 = (const float*)d_in[21];
    const float* W_u3 = (const float*)d_in[22]; const float* b_u3 = (const float*)d_in[23];

    const int n_users = in_sizes[0] / 128;
    const int n_tires = in_sizes[1] / 128;
    const int n_brand = in_sizes[2] / 128;
    const int n_size  = in_sizes[3] / 128;
    const int E       = in_sizes[8];

    float* out      = (float*)d_out;
    float* user_vec = out;
    float* item_vec = out + (size_t)n_users * 64;

    const int nbT = (n_tires + 63) / 64;
    const int nbU = (n_users + 63) / 64;

    const int SM128 = 2 * (64 + 128) * AST * 2;   // 55296 B
    const int SM64  = 2 * (64 + 64) * AST * 2;    // 36864 B
    cudaFuncSetAttribute(k_gemm<64, 384>,  cudaFuncAttributeMaxDynamicSharedMemorySize, SM64);
    cudaFuncSetAttribute(k_gemm<128, 256>, cudaFuncAttributeMaxDynamicSharedMemorySize, SM128);
    cudaFuncSetAttribute(k_gemm<128, 192>, cudaFuncAttributeMaxDynamicSharedMemorySize, SM128);
    cudaFuncSetAttribute(k_gemm<128, 128>, cudaFuncAttributeMaxDynamicSharedMemorySize, SM128);
    cudaFuncSetAttribute(k_gemm<64, 128>,  cudaFuncAttributeMaxDynamicSharedMemorySize, SM64);

    // 1. weight blobs (into g_wb device global)
    k_wsplit<<<(384 * 64  + 255) / 256, 256>>>(W_tp, WB_TP, 384, 64,  0);
    k_wsplit<<<(256 * 128 + 255) / 256, 256>>>(W_i1, WB_I1, 256, 128, 1);
    k_wsplit<<<(128 * 128 + 255) / 256, 256>>>(W_i2, WB_I2, 128, 128, 0);
    k_wsplit<<<(128 * 64  + 255) / 256, 256>>>(W_i3, WB_I3, 128, 64,  0);
    k_wsplit<<<(192 * 128 + 255) / 256, 256>>>(W_u1, WB_U1, 192, 128, 0);
    k_wsplit<<<(128 * 128 + 255) / 256, 256>>>(W_u2, WB_U2, 128, 128, 0);
    k_wsplit<<<(128 * 64  + 255) / 256, 256>>>(W_u3, WB_U3, 128, 64,  0);

    // 2. brand/size parts
    k_pre<<<n_brand + n_size, 128>>>(h_brand, h_size, W_i1, n_brand, n_size);

    // 3. text projection: text_emb -> g_tproj (dstSel 3)
    k_gemm<64, 384><<<nbT, 128, SM64>>>(
        text_emb, 384, 6, 0,  nullptr, 0, 0, 0,  nullptr, 0, 0,
        WB_TP, b_tp, 0, 3, 64, 0, nullptr, nullptr, nullptr, n_tires);

    // 4. item tower
    k_gemm<128, 256><<<nbT, 128, SM128>>>(
        h_tire, 128, 2, 0,  specs, 64, 1, 0,  nullptr, 64, 3,
        WB_I1, b_i1, 0, 1, 128, 1, bidx, sidx, nullptr, n_tires);
    k_gemm<128, 128><<<nbT, 128, SM128>>>(
        nullptr, 128, 2, 1,  nullptr, 0, 0, 0,  nullptr, 0, 0,
        WB_I2, b_i2, 0, 2, 128, 0, nullptr, nullptr, nullptr, n_tires);
    k_gemm<64, 128><<<nbT, 128, SM64>>>(
        nullptr, 128, 2, 2,  nullptr, 0, 0, 0,  nullptr, 0, 0,
        WB_I3, b_i3, 1, 0, 0, 0, nullptr, nullptr, item_vec, n_tires);

    // 5. history pool
    k_rowstart<<<(E + 255) / 256, 256>>>(hseg, E, n_users);
    k_hist<<<((size_t)n_users * 32 + 255) / 256, 256>>>(item_vec, hitems, n_users);

    // 6. user tower
    k_gemm<128, 192><<<nbU, 128, SM128>>>(
        h_user, 128, 2, 0,  nullptr, 64, 1, 4,  nullptr, 0, 0,
        WB_U1, b_u1, 0, 1, 128, 0, nullptr, nullptr, nullptr, n_users);
    k_gemm<128, 128><<<nbU, 128, SM128>>>(
        nullptr, 128, 2, 1,  nullptr, 0, 0, 0,  nullptr, 0, 0,
        WB_U2, b_u2, 0, 2, 128, 0, nullptr, nullptr, nullptr, n_users);
    k_gemm<64, 128><<<nbU, 128, SM64>>>(
        nullptr, 128, 2, 2,  nullptr, 0, 0, 0,  nullptr, 0, 0,
        WB_U3, b_u3, 1, 0, 0, 0, nullptr, nullptr, user_vec, n_users);
}

// round 16
// speedup vs baseline: 1.5796x; 1.0847x over previous
#include <cuda_runtime.h>
#include <cuda_bf16.h>
#include <math.h>
#include <cstdint>
#include <cstring>

// ---------------------------------------------------------------------------
// TwoTowerRecommender — split-bf16 mma.sync (m16n8k16), 3-pass hi/lo, fused
// per-tower kernels: L1->L2->L3 chained through smem (no interlayer global
// round trips). Named-register accumulators; no cudaGetSymbolAddress.
// Output: user_vec [U,64] then item_vec [T,64] (f32)
// ---------------------------------------------------------------------------

#define MAX_U 100000
#define ROWSPAD 100032

__device__ float g_hist_pool[(size_t)MAX_U * 64];
__device__ int   g_row_start[MAX_U + 1];
__device__ float g_brand_part[100 * 128];
__device__ float g_size_part[500 * 128];
__device__ __align__(16) float g_tproj[(size_t)ROWSPAD * 64];

#define WB_TP 0
#define WB_I1 49152
#define WB_I2 114688
#define WB_I3 147456
#define WB_U1 163840
#define WB_U2 212992
#define WB_U3 245760
__device__ __align__(16) __nv_bfloat16 g_wb[262144];

#define DINL __device__ __forceinline__

DINL __nv_bfloat16 bhi(float v) { return __float2bfloat16(v); }
DINL __nv_bfloat16 blo(float v, __nv_bfloat16 h) {
    return __float2bfloat16(v - __bfloat162float(h));
}
DINL uint32_t pk2(__nv_bfloat16 a, __nv_bfloat16 b) {
    uint32_t r;
    __nv_bfloat162 t;
    t.x = a; t.y = b;
    memcpy(&r, &t, 4);
    return r;
}

#define AST 72
#define HST 136
#define SM_TOWER (45056 * 2)
#define SM_TEXT  ((9216 + 9216) * 2)

#define MMA4(D, A0, A1, A2, A3, B0, B1)                                   \
    asm volatile(                                                         \
        "mma.sync.aligned.m16n8k16.row.col.f32.bf16.bf16.f32 "            \
        "{%0,%1,%2,%3}, {%4,%5,%6,%7}, {%8,%9}, {%0,%1,%2,%3};\n"         \
        : "+f"((D).x), "+f"((D).y), "+f"((D).z), "+f"((D).w)              \
        : "r"(A0), "r"(A1), "r"(A2), "r"(A3), "r"(B0), "r"(B1))

#define FORN8(E)  E(0) E(1) E(2) E(3) E(4) E(5) E(6) E(7)
#define FORN16(E) FORN8(E) E(8) E(9) E(10) E(11) E(12) E(13) E(14) E(15)
#define DRESET(i) d##i = make_float4(0.f, 0.f, 0.f, 0.f);

#define MMA_STEP(i) {                                                          \
    const __nv_bfloat16* bph = chB + ((i) * 8 + g) * AST;                      \
    const __nv_bfloat16* bpl = bsl + ((i) * 8 + g) * AST;                      \
    uint32_t bh0 = *(const uint32_t*)(bph + kb);                               \
    uint32_t bh1 = *(const uint32_t*)(bph + kb + 8);                           \
    uint32_t bl0 = *(const uint32_t*)(bpl + kb);                               \
    uint32_t bl1 = *(const uint32_t*)(bpl + kb + 8);                           \
    MMA4(d##i, ah0, ah1, ah2, ah3, bh0, bh1);                                  \
    MMA4(d##i, ah0, ah1, ah2, ah3, bl0, bl1);                                  \
    MMA4(d##i, al0, al1, al2, al3, bh0, bh1);                                  \
}

#define MMA_CHUNK(FORN, ABASE, STRD, KOFF)                                     \
    _Pragma("unroll")                                                          \
    for (int kk = 0; kk < 4; kk++) {                                           \
        const int kb = kk * 16 + q * 2;                                        \
        const int k0 = kb + (KOFF);                                            \
        const int r0 = rb + g, r1 = r0 + 8;                                    \
        const __nv_bfloat16* ahb = (ABASE);                                    \
        const __nv_bfloat16* alb = (ABASE) + 64 * (STRD);                      \
        uint32_t ah0 = *(const uint32_t*)(ahb + r0 * (STRD) + k0);             \
        uint32_t ah1 = *(const uint32_t*)(ahb + r1 * (STRD) + k0);             \
        uint32_t ah2 = *(const uint32_t*)(ahb + r0 * (STRD) + k0 + 8);         \
        uint32_t ah3 = *(const uint32_t*)(ahb + r1 * (STRD) + k0 + 8);         \
        uint32_t al0 = *(const uint32_t*)(alb + r0 * (STRD) + k0);             \
        uint32_t al1 = *(const uint32_t*)(alb + r1 * (STRD) + k0);             \
        uint32_t al2 = *(const uint32_t*)(alb + r0 * (STRD) + k0 + 8);         \
        uint32_t al3 = *(const uint32_t*)(alb + r1 * (STRD) + k0 + 8);         \
        FORN(MMA_STEP)                                                         \
    }

#define STAGE_B(WOFF, KK, NN)                                                  \
    for (int i = t; i < 2 * (NN) * 16; i += 128) {                             \
        int sp = i / ((NN) * 16);                                              \
        int rem = i - sp * (NN) * 16;                                          \
        int r = rem >> 4, u = rem & 15;                                        \
        *(unsigned long long*)(chB + sp * (NN) * AST + r * AST + u * 4) =      \
            *(const unsigned long long*)(g_wb + (WOFF) +                       \
                ((size_t)sp * (NN) + r) * (KK) + (size_t)ch * 64 + u * 4);     \
    }

#define STAGE_A()                                                              \
    for (int i = t; i < 1024; i += 128) {                                      \
        int r = i >> 4, u = i & 15;                                            \
        int sr = blk * 64 + r;                                                 \
        if (sr >= nrows) sr = nrows - 1;                                       \
        float4 v = *(const float4*)(csrc + (size_t)sr * cstride + coff + u * 4); \
        __nv_bfloat16 h0 = bhi(v.x), l0 = blo(v.x, h0);                        \
        __nv_bfloat16 h1 = bhi(v.y), l1 = blo(v.y, h1);                        \
        __nv_bfloat16 h2 = bhi(v.z), l2 = blo(v.z, h2);                        \
        __nv_bfloat16 h3 = bhi(v.w), l3 = blo(v.w, h3);                        \
        *(uint32_t*)(chA + r * AST + u * 4)            = pk2(h0, h1);          \
        *(uint32_t*)(chA + r * AST + u * 4 + 2)        = pk2(h2, h3);          \
        *(uint32_t*)(chA + 64 * AST + r * AST + u * 4)     = pk2(l0, l1);      \
        *(uint32_t*)(chA + 64 * AST + r * AST + u * 4 + 2) = pk2(l2, l3);      \
    }

__global__ void k_wsplit(const float* __restrict__ src, int off,
                         int K, int N, int remap)
{
    int idx = blockIdx.x * blockDim.x + threadIdx.x;
    if (idx >= K * N) return;
    int k = idx / N, n = idx % N;
    int sr = (remap && k >= 128) ? k + 256 : k;
    float v = src[(size_t)sr * N + n];
    __nv_bfloat16 h = bhi(v), l = blo(v, h);
    g_wb[off + (size_t)n * K + k] = h;
    g_wb[off + ((size_t)N + n) * K + k] = l;
}

__global__ void __launch_bounds__(128) k_text(
    const float* __restrict__ text, const float* __restrict__ bias, int nrows)
{
    extern __shared__ __nv_bfloat16 smT[];
    __nv_bfloat16* const chA = smT;
    __nv_bfloat16* const chB = smT + 9216;
    const __nv_bfloat16* const bsl = chB + 64 * AST;

    const int t = threadIdx.x, wid = t >> 5, lane = t & 31;
    const int g = lane >> 2, q = lane & 3;
    const int blk = blockIdx.x;
    const int rb = wid * 16;

    float4 d0, d1, d2, d3, d4, d5, d6, d7;
    FORN8(DRESET)

    for (int ch = 0; ch < 6; ch++) {
        __syncthreads();
        const float* csrc = text;
        const int cstride = 384, coff = ch * 64;
        STAGE_A()
        STAGE_B(WB_TP, 384, 64)
        __syncthreads();
        MMA_CHUNK(FORN8, chA, AST, 0)
    }

    const int grow0 = blk * 64 + rb + g;
    const int grow1 = grow0 + 8;
#define EPI_T(i) {                                                             \
    int c0 = (i) * 8 + q * 2;                                                  \
    float b0 = bias[c0], b1 = bias[c0 + 1];                                    \
    *(float2*)(g_tproj + (size_t)grow0 * 64 + c0) =                            \
        make_float2(fmaxf(d##i.x + b0, 0.f), fmaxf(d##i.y + b1, 0.f));         \
    *(float2*)(g_tproj + (size_t)grow1 * 64 + c0) =                            \
        make_float2(fmaxf(d##i.z + b0, 0.f), fmaxf(d##i.w + b1, 0.f)); }
    FORN8(EPI_T)
#undef EPI_T
}

// Fused 3-layer tower. L1 chunk sources: ch<chAc -> srcA;
// itemMode: ch==chAc -> specsPtr (stride 64), ch==chAc+1 -> g_tproj;
// !itemMode: ch>=chAc -> g_hist_pool.
template<int K1>
__global__ void __launch_bounds__(128) k_tower(
    const float* __restrict__ srcA, int sA, int chAc,
    const float* __restrict__ specsPtr, int itemMode,
    int wb1, const float* __restrict__ b1v,
    int useParts, const int* __restrict__ bidx, const int* __restrict__ sidx,
    int wb2, const float* __restrict__ b2v,
    int wb3, const float* __restrict__ b3v,
    float* __restrict__ outp, int nrows)
{
    constexpr int NCH1 = K1 / 64;
    extern __shared__ __nv_bfloat16 smW[];
    __nv_bfloat16* const chA  = smW;
    __nv_bfloat16* const chB  = smW + 9216;
    __nv_bfloat16* const hbuf = smW + 27648;

    const int t = threadIdx.x, wid = t >> 5, lane = t & 31;
    const int g = lane >> 2, q = lane & 3;
    const int blk = blockIdx.x;
    const int rb = wid * 16;

    float4 d0, d1, d2, d3, d4, d5, d6, d7, d8, d9, d10, d11, d12, d13, d14, d15;
    FORN16(DRESET)

    // ================= L1 =================
    {
        const __nv_bfloat16* const bsl = chB + 128 * AST;
        for (int ch = 0; ch < NCH1; ch++) {
            __syncthreads();
            const float* csrc;
            int cstride, coff;
            if (ch < chAc) { csrc = srcA; cstride = sA; coff = ch * 64; }
            else if (itemMode) {
                if (ch == chAc) { csrc = specsPtr; cstride = 64; coff = 0; }
                else            { csrc = g_tproj;  cstride = 64; coff = 0; }
            } else { csrc = g_hist_pool; cstride = 64; coff = 0; }
            STAGE_A()
            STAGE_B(wb1, K1, 128)
            __syncthreads();
            MMA_CHUNK(FORN16, chA, AST, 0)
        }
        __syncthreads();
        const int grow0 = blk * 64 + rb + g;
        const int grow1 = grow0 + 8;
        const float *bp0 = g_brand_part, *zp0 = g_size_part;
        const float *bp1 = g_brand_part, *zp1 = g_size_part;
        if (useParts) {
            int rr0 = grow0 < nrows ? grow0 : nrows - 1;
            int rr1 = grow1 < nrows ? grow1 : nrows - 1;
            bp0 = g_brand_part + (size_t)bidx[rr0] * 128;
            zp0 = g_size_part  + (size_t)sidx[rr0] * 128;
            bp1 = g_brand_part + (size_t)bidx[rr1] * 128;
            zp1 = g_size_part  + (size_t)sidx[rr1] * 128;
        }
        const int r0 = rb + g, r1 = r0 + 8;
        __nv_bfloat16* const hhi = hbuf;
        __nv_bfloat16* const hlo = hbuf + 64 * HST;
#define EPI_1(i) {                                                             \
        int c0 = (i) * 8 + q * 2;                                              \
        float b0 = b1v[c0], b1_ = b1v[c0 + 1];                                 \
        float v00 = d##i.x + b0, v01 = d##i.y + b1_;                           \
        float v10 = d##i.z + b0, v11 = d##i.w + b1_;                           \
        if (useParts) {                                                        \
            v00 += bp0[c0] + zp0[c0];     v01 += bp0[c0 + 1] + zp0[c0 + 1];    \
            v10 += bp1[c0] + zp1[c0];     v11 += bp1[c0 + 1] + zp1[c0 + 1];    \
        }                                                                      \
        v00 = fmaxf(v00, 0.f); v01 = fmaxf(v01, 0.f);                          \
        v10 = fmaxf(v10, 0.f); v11 = fmaxf(v11, 0.f);                          \
        __nv_bfloat16 h00 = bhi(v00), l00 = blo(v00, h00);                     \
        __nv_bfloat16 h01 = bhi(v01), l01 = blo(v01, h01);                     \
        __nv_bfloat16 h10 = bhi(v10), l10 = blo(v10, h10);                     \
        __nv_bfloat16 h11 = bhi(v11), l11 = blo(v11, h11);                     \
        *(uint32_t*)(hhi + r0 * HST + c0) = pk2(h00, h01);                     \
        *(uint32_t*)(hhi + r1 * HST + c0) = pk2(h10, h11);                     \
        *(uint32_t*)(hlo + r0 * HST + c0) = pk2(l00, l01);                     \
        *(uint32_t*)(hlo + r1 * HST + c0) = pk2(l10, l11); }
        FORN16(EPI_1)
#undef EPI_1
    }
    FORN16(DRESET)
    __syncthreads();

    // ================= L2 =================
    {
        const __nv_bfloat16* const bsl = chB + 128 * AST;
        for (int ch = 0; ch < 2; ch++) {
            __syncthreads();
            STAGE_B(wb2, 128, 128)
            __syncthreads();
            MMA_CHUNK(FORN16, hbuf, HST, ch * 64)
        }
        __syncthreads();
        const int r0 = rb + g, r1 = r0 + 8;
        __nv_bfloat16* const hhi = hbuf;
        __nv_bfloat16* const hlo = hbuf + 64 * HST;
#define EPI_2(i) {                                                             \
        int c0 = (i) * 8 + q * 2;                                              \
        float b0 = b2v[c0], b1_ = b2v[c0 + 1];                                 \
        float v00 = fmaxf(d##i.x + b0, 0.f), v01 = fmaxf(d##i.y + b1_, 0.f);   \
        float v10 = fmaxf(d##i.z + b0, 0.f), v11 = fmaxf(d##i.w + b1_, 0.f);   \
        __nv_bfloat16 h00 = bhi(v00), l00 = blo(v00, h00);                     \
        __nv_bfloat16 h01 = bhi(v01), l01 = blo(v01, h01);                     \
        __nv_bfloat16 h10 = bhi(v10), l10 = blo(v10, h10);                     \
        __nv_bfloat16 h11 = bhi(v11), l11 = blo(v11, h11);                     \
        *(uint32_t*)(hhi + r0 * HST + c0) = pk2(h00, h01);                     \
        *(uint32_t*)(hhi + r1 * HST + c0) = pk2(h10, h11);                     \
        *(uint32_t*)(hlo + r0 * HST + c0) = pk2(l00, l01);                     \
        *(uint32_t*)(hlo + r1 * HST + c0) = pk2(l10, l11); }
        FORN16(EPI_2)
#undef EPI_2
    }
    FORN16(DRESET)
    __syncthreads();

    // ================= L3 + l2norm =================
    {
        const __nv_bfloat16* const bsl = chB + 64 * AST;
        for (int ch = 0; ch < 2; ch++) {
            __syncthreads();
            STAGE_B(wb3, 128, 64)
            __syncthreads();
            MMA_CHUNK(FORN8, hbuf, HST, ch * 64)
        }
        const int grow0 = blk * 64 + rb + g;
        const int grow1 = grow0 + 8;
        float ss0 = 0.0f, ss1 = 0.0f;
#define EPI_N(i) {                                                             \
        int c0 = (i) * 8 + q * 2;                                              \
        float b0 = b3v[c0], b1_ = b3v[c0 + 1];                                 \
        d##i.x += b0; d##i.y += b1_; d##i.z += b0; d##i.w += b1_;              \
        ss0 += d##i.x * d##i.x + d##i.y * d##i.y;                              \
        ss1 += d##i.z * d##i.z + d##i.w * d##i.w; }
        FORN8(EPI_N)
#undef EPI_N
        ss0 += __shfl_xor_sync(0xFFFFFFFFu, ss0, 1);
        ss0 += __shfl_xor_sync(0xFFFFFFFFu, ss0, 2);
        ss1 += __shfl_xor_sync(0xFFFFFFFFu, ss1, 1);
        ss1 += __shfl_xor_sync(0xFFFFFFFFu, ss1, 2);
        float inv0 = 1.0f / fmaxf(sqrtf(ss0), 1e-12f);
        float inv1 = 1.0f / fmaxf(sqrtf(ss1), 1e-12f);
#define EPI_NS(i) {                                                            \
        if (grow0 < nrows)                                                     \
            *(float2*)(outp + (size_t)grow0 * 64 + (i) * 8 + q * 2) =          \
                make_float2(d##i.x * inv0, d##i.y * inv0);                     \
        if (grow1 < nrows)                                                     \
            *(float2*)(outp + (size_t)grow1 * 64 + (i) * 8 + q * 2) =          \
                make_float2(d##i.z * inv1, d##i.w * inv1); }
        FORN8(EPI_NS)
#undef EPI_NS
    }
}

__global__ void __launch_bounds__(128) k_pre(
    const float* __restrict__ hb, const float* __restrict__ hz,
    const float* __restrict__ W1, int n_brand, int n_size)
{
    __shared__ float rowv[128];
    const int t = threadIdx.x;
    const int r = blockIdx.x;
    const float* src;
    const float* W;
    float* dst;
    if (r < n_brand) {
        src = hb + (size_t)r * 128; W = W1 + (size_t)128 * 128; dst = g_brand_part + (size_t)r * 128;
    } else {
        int rr = r - n_brand;
        src = hz + (size_t)rr * 128; W = W1 + (size_t)256 * 128; dst = g_size_part + (size_t)rr * 128;
    }
    rowv[t] = src[t];
    __syncthreads();
    float a = 0.0f;
#pragma unroll 4
    for (int k = 0; k < 128; k++) a = fmaf(rowv[k], W[(size_t)k * 128 + t], a);
    dst[t] = a;
}

__global__ void k_rowstart(const int* __restrict__ seg, int E, int n_users)
{
    int e = blockIdx.x * blockDim.x + threadIdx.x;
    if (e >= E) return;
    int s = seg[e];
    int p = (e == 0) ? -1 : seg[e - 1];
    for (int u = p + 1; u <= s; ++u) g_row_start[u] = e;
    if (e == E - 1) {
        for (int u = s + 1; u <= n_users; ++u) g_row_start[u] = E;
    }
}

__global__ void k_hist(const float* __restrict__ item_vec,
                       const int* __restrict__ items, int n_users)
{
    int gw   = (blockIdx.x * blockDim.x + threadIdx.x) >> 5;
    int lane = threadIdx.x & 31;
    if (gw >= n_users) return;
    int s = g_row_start[gw], e = g_row_start[gw + 1];
    float a0 = 0.0f, a1 = 0.0f;
    if (e > s) {
        int it = items[s];
        for (int j = s; j < e; ++j) {
            int nx = (j + 1 < e) ? items[j + 1] : 0;
            const float* p = item_vec + (size_t)it * 64;
            a0 += p[lane];
            a1 += p[32 + lane];
            it = nx;
        }
        float inv = 1.0f / (float)(e - s);
        a0 *= inv; a1 *= inv;
    }
    g_hist_pool[(size_t)gw * 64 + lane]      = a0;
    g_hist_pool[(size_t)gw * 64 + 32 + lane] = a1;
}

extern "C" void kernel_launch(void* const* d_in, const int* in_sizes, int n_in,
                              void* d_out, int out_size)
{
    const float* h_user   = (const float*)d_in[0];
    const float* h_tire   = (const float*)d_in[1];
    const float* h_brand  = (const float*)d_in[2];
    const float* h_size   = (const float*)d_in[3];
    const float* specs    = (const float*)d_in[4];
    const float* text_emb = (const float*)d_in[5];
    const int*   bidx     = (const int*)d_in[6];
    const int*   sidx     = (const int*)d_in[7];
    const int*   hitems   = (const int*)d_in[8];
    const int*   hseg     = (const int*)d_in[9];
    const float* W_tp = (const float*)d_in[10]; const float* b_tp = (const float*)d_in[11];
    const float* W_i1 = (const float*)d_in[12]; const float* b_i1 = (const float*)d_in[13];
    const float* W_i2 = (const float*)d_in[14]; const float* b_i2 = (const float*)d_in[15];
    const float* W_i3 = (const float*)d_in[16]; const float* b_i3 = (const float*)d_in[17];
    const float* W_u1 = (const float*)d_in[18]; const float* b_u1 = (const float*)d_in[19];
    const float* W_u2 = (const float*)d_in[20]; const float* b_u2 = (const float*)d_in[21];
    const float* W_u3 = (const float*)d_in[22]; const float* b_u3 = (const float*)d_in[23];

    const int n_users = in_sizes[0] / 128;
    const int n_tires = in_sizes[1] / 128;
    const int n_brand = in_sizes[2] / 128;
    const int n_size  = in_sizes[3] / 128;
    const int E       = in_sizes[8];

    float* out      = (float*)d_out;
    float* user_vec = out;
    float* item_vec = out + (size_t)n_users * 64;

    const int nbT = (n_tires + 63) / 64;
    const int nbU = (n_users + 63) / 64;

    cudaFuncSetAttribute(k_text, cudaFuncAttributeMaxDynamicSharedMemorySize, SM_TEXT);
    cudaFuncSetAttribute(k_tower<256>, cudaFuncAttributeMaxDynamicSharedMemorySize, SM_TOWER);
    cudaFuncSetAttribute(k_tower<192>, cudaFuncAttributeMaxDynamicSharedMemorySize, SM_TOWER);

    k_wsplit<<<(384 * 64  + 255) / 256, 256>>>(W_tp, WB_TP, 384, 64,  0);
    k_wsplit<<<(256 * 128 + 255) / 256, 256>>>(W_i1, WB_I1, 256, 128, 1);
    k_wsplit<<<(128 * 128 + 255) / 256, 256>>>(W_i2, WB_I2, 128, 128, 0);
    k_wsplit<<<(128 * 64  + 255) / 256, 256>>>(W_i3, WB_I3, 128, 64,  0);
    k_wsplit<<<(192 * 128 + 255) / 256, 256>>>(W_u1, WB_U1, 192, 128, 0);
    k_wsplit<<<(128 * 128 + 255) / 256, 256>>>(W_u2, WB_U2, 128, 128, 0);
    k_wsplit<<<(128 * 64  + 255) / 256, 256>>>(W_u3, WB_U3, 128, 64,  0);

    k_pre<<<n_brand + n_size, 128>>>(h_brand, h_size, W_i1, n_brand, n_size);

    k_text<<<nbT, 128, SM_TEXT>>>(text_emb, b_tp, n_tires);

    k_tower<256><<<nbT, 128, SM_TOWER>>>(
        h_tire, 128, 2, specs, 1,
        WB_I1, b_i1, 1, bidx, sidx,
        WB_I2, b_i2, WB_I3, b_i3,
        item_vec, n_tires);

    k_rowstart<<<(E + 255) / 256, 256>>>(hseg, E, n_users);
    k_hist<<<((size_t)n_users * 32 + 255) / 256, 256>>>(item_vec, hitems, n_users);

    k_tower<192><<<nbU, 128, SM_TOWER>>>(
        h_user, 128, 2, nullptr, 0,
        WB_U1, b_u1, 0, nullptr, nullptr,
        WB_U2, b_u2, WB_U3, b_u3,
        user_vec, n_users);
}

// round 17
// speedup vs baseline: 1.6195x; 1.0253x over previous
#include <cuda_runtime.h>
#include <cuda_bf16.h>
#include <math.h>
#include <cstdint>
#include <cstring>

// ---------------------------------------------------------------------------
// TwoTowerRecommender — split-bf16 mma.sync (m16n8k16), 3-pass hi/lo, fused
// towers with REGISTER-RESIDENT interlayer activations: warp's D-fragment
// rows/cols == next layer's A-fragment rows/cols, so h1/h2 live as packed
// hi/lo bf16 fragments in named registers (no hbuf smem, no interlayer syncs).
// Output: user_vec [U,64] then item_vec [T,64] (f32)
// ---------------------------------------------------------------------------

#define MAX_U 100000
#define ROWSPAD 100032

__device__ float g_hist_pool[(size_t)MAX_U * 64];
__device__ int   g_row_start[MAX_U + 1];
__device__ float g_brand_part[100 * 128];
__device__ float g_size_part[500 * 128];
__device__ __align__(16) float g_tproj[(size_t)ROWSPAD * 64];

#define WB_TP 0
#define WB_I1 49152
#define WB_I2 114688
#define WB_I3 147456
#define WB_U1 163840
#define WB_U2 212992
#define WB_U3 245760
__device__ __align__(16) __nv_bfloat16 g_wb[262144];

#define DINL __device__ __forceinline__

DINL __nv_bfloat16 bhi(float v) { return __float2bfloat16(v); }
DINL __nv_bfloat16 blo(float v, __nv_bfloat16 h) {
    return __float2bfloat16(v - __bfloat162float(h));
}
DINL uint32_t pk2(__nv_bfloat16 a, __nv_bfloat16 b) {
    uint32_t r;
    __nv_bfloat162 t;
    t.x = a; t.y = b;
    memcpy(&r, &t, 4);
    return r;
}

#define AST 72
// smem: chA [2][64][72] = 9216 elems, chB [2][128][72] = 18432 elems
#define SM_TOWER ((9216 + 18432) * 2)   // 55296 B
#define SM_TEXT  ((9216 + 9216) * 2)

#define MMA4(D, A0, A1, A2, A3, B0, B1)                                   \
    asm volatile(                                                         \
        "mma.sync.aligned.m16n8k16.row.col.f32.bf16.bf16.f32 "            \
        "{%0,%1,%2,%3}, {%4,%5,%6,%7}, {%8,%9}, {%0,%1,%2,%3};\n"         \
        : "+f"((D).x), "+f"((D).y), "+f"((D).z), "+f"((D).w)              \
        : "r"(A0), "r"(A1), "r"(A2), "r"(A3), "r"(B0), "r"(B1))

#define FORN8(E)  E(0) E(1) E(2) E(3) E(4) E(5) E(6) E(7)
#define FORN16(E) FORN8(E) E(8) E(9) E(10) E(11) E(12) E(13) E(14) E(15)
#define DRESET(i) d##i = make_float4(0.f, 0.f, 0.f, 0.f);
#define DECL_F(i) uint32_t fh0_##i, fh1_##i, fl0_##i, fl1_##i;

// 3-pass MMA for output tile i; ah*/al*/kb/g/chB/bsl from scope.
#define MMA_STEP(i) {                                                          \
    const __nv_bfloat16* bph = chB + ((i) * 8 + g) * AST;                      \
    const __nv_bfloat16* bpl = bsl + ((i) * 8 + g) * AST;                      \
    uint32_t bh0 = *(const uint32_t*)(bph + kb);                               \
    uint32_t bh1 = *(const uint32_t*)(bph + kb + 8);                           \
    uint32_t bl0 = *(const uint32_t*)(bpl + kb);                               \
    uint32_t bl1 = *(const uint32_t*)(bpl + kb + 8);                           \
    MMA4(d##i, ah0, ah1, ah2, ah3, bh0, bh1);                                  \
    MMA4(d##i, ah0, ah1, ah2, ah3, bl0, bl1);                                  \
    MMA4(d##i, al0, al1, al2, al3, bh0, bh1);                                  \
}

// One k-step with A from smem chunk buffer (L1/text).
#define MMA_CHUNK_SM(FORN)                                                     \
    _Pragma("unroll")                                                          \
    for (int kk = 0; kk < 4; kk++) {                                           \
        const int kb = kk * 16 + q * 2;                                        \
        const int r0 = rb + g, r1 = r0 + 8;                                    \
        const __nv_bfloat16* alb = chA + 64 * AST;                             \
        uint32_t ah0 = *(const uint32_t*)(chA + r0 * AST + kb);                \
        uint32_t ah1 = *(const uint32_t*)(chA + r1 * AST + kb);                \
        uint32_t ah2 = *(const uint32_t*)(chA + r0 * AST + kb + 8);            \
        uint32_t ah3 = *(const uint32_t*)(chA + r1 * AST + kb + 8);            \
        uint32_t al0 = *(const uint32_t*)(alb + r0 * AST + kb);                \
        uint32_t al1 = *(const uint32_t*)(alb + r1 * AST + kb);                \
        uint32_t al2 = *(const uint32_t*)(alb + r0 * AST + kb + 8);            \
        uint32_t al3 = *(const uint32_t*)(alb + r1 * AST + kb + 8);            \
        FORN(MMA_STEP)                                                         \
    }

// One k-step with A from register fragments (tiles IA, IB). KK in 0..3.
#define MMA_KSTEP_REG(FORN, KK, IA, IB) {                                      \
    const int kb = (KK) * 16 + q * 2;                                          \
    uint32_t ah0 = fh0_##IA, ah1 = fh1_##IA, ah2 = fh0_##IB, ah3 = fh1_##IB;   \
    uint32_t al0 = fl0_##IA, al1 = fl1_##IA, al2 = fl0_##IB, al3 = fl1_##IB;   \
    FORN(MMA_STEP)                                                             \
}

#define STAGE_B(WOFF, KK, NN)                                                  \
    for (int i = t; i < 2 * (NN) * 16; i += 128) {                             \
        int sp = i / ((NN) * 16);                                              \
        int rem = i - sp * (NN) * 16;                                          \
        int r = rem >> 4, u = rem & 15;                                        \
        *(unsigned long long*)(chB + sp * (NN) * AST + r * AST + u * 4) =      \
            *(const unsigned long long*)(g_wb + (WOFF) +                       \
                ((size_t)sp * (NN) + r) * (KK) + (size_t)ch * 64 + u * 4);     \
    }

#define STAGE_A()                                                              \
    for (int i = t; i < 1024; i += 128) {                                      \
        int r = i >> 4, u = i & 15;                                            \
        int sr = blk * 64 + r;                                                 \
        if (sr >= nrows) sr = nrows - 1;                                       \
        float4 v = *(const float4*)(csrc + (size_t)sr * cstride + coff + u * 4); \
        __nv_bfloat16 h0 = bhi(v.x), l0 = blo(v.x, h0);                        \
        __nv_bfloat16 h1 = bhi(v.y), l1 = blo(v.y, h1);                        \
        __nv_bfloat16 h2 = bhi(v.z), l2 = blo(v.z, h2);                        \
        __nv_bfloat16 h3 = bhi(v.w), l3 = blo(v.w, h3);                        \
        *(uint32_t*)(chA + r * AST + u * 4)            = pk2(h0, h1);          \
        *(uint32_t*)(chA + r * AST + u * 4 + 2)        = pk2(h2, h3);          \
        *(uint32_t*)(chA + 64 * AST + r * AST + u * 4)     = pk2(l0, l1);      \
        *(uint32_t*)(chA + 64 * AST + r * AST + u * 4 + 2) = pk2(l2, l3);      \
    }

__global__ void k_wsplit(const float* __restrict__ src, int off,
                         int K, int N, int remap)
{
    int idx = blockIdx.x * blockDim.x + threadIdx.x;
    if (idx >= K * N) return;
    int k = idx / N, n = idx % N;
    int sr = (remap && k >= 128) ? k + 256 : k;
    float v = src[(size_t)sr * N + n];
    __nv_bfloat16 h = bhi(v), l = blo(v, h);
    g_wb[off + (size_t)n * K + k] = h;
    g_wb[off + ((size_t)N + n) * K + k] = l;
}

__global__ void __launch_bounds__(128) k_text(
    const float* __restrict__ text, const float* __restrict__ bias, int nrows)
{
    extern __shared__ __nv_bfloat16 smT[];
    __nv_bfloat16* const chA = smT;
    __nv_bfloat16* const chB = smT + 9216;
    const __nv_bfloat16* const bsl = chB + 64 * AST;

    const int t = threadIdx.x, wid = t >> 5, lane = t & 31;
    const int g = lane >> 2, q = lane & 3;
    const int blk = blockIdx.x;
    const int rb = wid * 16;

    float4 d0, d1, d2, d3, d4, d5, d6, d7;
    FORN8(DRESET)

    for (int ch = 0; ch < 6; ch++) {
        __syncthreads();
        const float* csrc = text;
        const int cstride = 384, coff = ch * 64;
        STAGE_A()
        STAGE_B(WB_TP, 384, 64)
        __syncthreads();
        MMA_CHUNK_SM(FORN8)
    }

    const int grow0 = blk * 64 + rb + g;
    const int grow1 = grow0 + 8;
#define EPI_T(i) {                                                             \
    int c0 = (i) * 8 + q * 2;                                                  \
    float b0 = bias[c0], b1 = bias[c0 + 1];                                    \
    *(float2*)(g_tproj + (size_t)grow0 * 64 + c0) =                            \
        make_float2(fmaxf(d##i.x + b0, 0.f), fmaxf(d##i.y + b1, 0.f));         \
    *(float2*)(g_tproj + (size_t)grow1 * 64 + c0) =                            \
        make_float2(fmaxf(d##i.z + b0, 0.f), fmaxf(d##i.w + b1, 0.f)); }
    FORN8(EPI_T)
#undef EPI_T
}

// Fused tower; interlayer h as register fragments.
template<int K1>
__global__ void __launch_bounds__(128) k_tower(
    const float* __restrict__ srcA, int sA, int chAc,
    const float* __restrict__ specsPtr, int itemMode,
    int wb1, const float* __restrict__ b1v,
    int useParts, const int* __restrict__ bidx, const int* __restrict__ sidx,
    int wb2, const float* __restrict__ b2v,
    int wb3, const float* __restrict__ b3v,
    float* __restrict__ outp, int nrows)
{
    constexpr int NCH1 = K1 / 64;
    extern __shared__ __nv_bfloat16 smW[];
    __nv_bfloat16* const chA = smW;
    __nv_bfloat16* const chB = smW + 9216;

    const int t = threadIdx.x, wid = t >> 5, lane = t & 31;
    const int g = lane >> 2, q = lane & 3;
    const int blk = blockIdx.x;
    const int rb = wid * 16;

    float4 d0, d1, d2, d3, d4, d5, d6, d7, d8, d9, d10, d11, d12, d13, d14, d15;
    FORN16(DRESET)
    FORN16(DECL_F)

    const int grow0 = blk * 64 + rb + g;
    const int grow1 = grow0 + 8;

    // ================= L1: K1 -> 128, relu (+parts) -> register frags ======
    {
        const __nv_bfloat16* const bsl = chB + 128 * AST;
        for (int ch = 0; ch < NCH1; ch++) {
            __syncthreads();
            const float* csrc;
            int cstride, coff;
            if (ch < chAc) { csrc = srcA; cstride = sA; coff = ch * 64; }
            else if (itemMode) {
                if (ch == chAc) { csrc = specsPtr; cstride = 64; coff = 0; }
                else            { csrc = g_tproj;  cstride = 64; coff = 0; }
            } else { csrc = g_hist_pool; cstride = 64; coff = 0; }
            STAGE_A()
            STAGE_B(wb1, K1, 128)
            __syncthreads();
            MMA_CHUNK_SM(FORN16)
        }
        const float *bp0 = g_brand_part, *zp0 = g_size_part;
        const float *bp1 = g_brand_part, *zp1 = g_size_part;
        if (useParts) {
            int rr0 = grow0 < nrows ? grow0 : nrows - 1;
            int rr1 = grow1 < nrows ? grow1 : nrows - 1;
            bp0 = g_brand_part + (size_t)bidx[rr0] * 128;
            zp0 = g_size_part  + (size_t)sidx[rr0] * 128;
            bp1 = g_brand_part + (size_t)bidx[rr1] * 128;
            zp1 = g_size_part  + (size_t)sidx[rr1] * 128;
        }
#define EPI_1(i) {                                                             \
        int c0 = (i) * 8 + q * 2;                                              \
        float b0 = b1v[c0], b1_ = b1v[c0 + 1];                                 \
        float v00 = d##i.x + b0, v01 = d##i.y + b1_;                           \
        float v10 = d##i.z + b0, v11 = d##i.w + b1_;                           \
        if (useParts) {                                                        \
            v00 += bp0[c0] + zp0[c0];     v01 += bp0[c0 + 1] + zp0[c0 + 1];    \
            v10 += bp1[c0] + zp1[c0];     v11 += bp1[c0 + 1] + zp1[c0 + 1];    \
        }                                                                      \
        v00 = fmaxf(v00, 0.f); v01 = fmaxf(v01, 0.f);                          \
        v10 = fmaxf(v10, 0.f); v11 = fmaxf(v11, 0.f);                          \
        __nv_bfloat16 h00 = bhi(v00), h01 = bhi(v01);                          \
        __nv_bfloat16 h10 = bhi(v10), h11 = bhi(v11);                          \
        fh0_##i = pk2(h00, h01); fh1_##i = pk2(h10, h11);                      \
        fl0_##i = pk2(blo(v00, h00), blo(v01, h01));                           \
        fl1_##i = pk2(blo(v10, h10), blo(v11, h11)); }
        FORN16(EPI_1)
#undef EPI_1
    }
    FORN16(DRESET)

    // ================= L2: 128 -> 128 relu (A = register frags) ============
    {
        const __nv_bfloat16* const bsl = chB + 128 * AST;
        {
            int ch = 0;
            __syncthreads();
            STAGE_B(wb2, 128, 128)
            __syncthreads();
            MMA_KSTEP_REG(FORN16, 0, 0, 1)
            MMA_KSTEP_REG(FORN16, 1, 2, 3)
            MMA_KSTEP_REG(FORN16, 2, 4, 5)
            MMA_KSTEP_REG(FORN16, 3, 6, 7)
        }
        {
            int ch = 1;
            __syncthreads();
            STAGE_B(wb2, 128, 128)
            __syncthreads();
            MMA_KSTEP_REG(FORN16, 0, 8, 9)
            MMA_KSTEP_REG(FORN16, 1, 10, 11)
            MMA_KSTEP_REG(FORN16, 2, 12, 13)
            MMA_KSTEP_REG(FORN16, 3, 14, 15)
        }
#define EPI_2(i) {                                                             \
        int c0 = (i) * 8 + q * 2;                                              \
        float b0 = b2v[c0], b1_ = b2v[c0 + 1];                                 \
        float v00 = fmaxf(d##i.x + b0, 0.f), v01 = fmaxf(d##i.y + b1_, 0.f);   \
        float v10 = fmaxf(d##i.z + b0, 0.f), v11 = fmaxf(d##i.w + b1_, 0.f);   \
        __nv_bfloat16 h00 = bhi(v00), h01 = bhi(v01);                          \
        __nv_bfloat16 h10 = bhi(v10), h11 = bhi(v11);                          \
        fh0_##i = pk2(h00, h01); fh1_##i = pk2(h10, h11);                      \
        fl0_##i = pk2(blo(v00, h00), blo(v01, h01));                           \
        fl1_##i = pk2(blo(v10, h10), blo(v11, h11)); }
        FORN16(EPI_2)
#undef EPI_2
    }
    FORN16(DRESET)

    // ================= L3: 128 -> 64, l2norm ===============================
    {
        const __nv_bfloat16* const bsl = chB + 64 * AST;
        {
            int ch = 0;
            __syncthreads();
            STAGE_B(wb3, 128, 64)
            __syncthreads();
            MMA_KSTEP_REG(FORN8, 0, 0, 1)
            MMA_KSTEP_REG(FORN8, 1, 2, 3)
            MMA_KSTEP_REG(FORN8, 2, 4, 5)
            MMA_KSTEP_REG(FORN8, 3, 6, 7)
        }
        {
            int ch = 1;
            __syncthreads();
            STAGE_B(wb3, 128, 64)
            __syncthreads();
            MMA_KSTEP_REG(FORN8, 0, 8, 9)
            MMA_KSTEP_REG(FORN8, 1, 10, 11)
            MMA_KSTEP_REG(FORN8, 2, 12, 13)
            MMA_KSTEP_REG(FORN8, 3, 14, 15)
        }
        float ss0 = 0.0f, ss1 = 0.0f;
#define EPI_N(i) {                                                             \
        int c0 = (i) * 8 + q * 2;                                              \
        float b0 = b3v[c0], b1_ = b3v[c0 + 1];                                 \
        d##i.x += b0; d##i.y += b1_; d##i.z += b0; d##i.w += b1_;              \
        ss0 += d##i.x * d##i.x + d##i.y * d##i.y;                              \
        ss1 += d##i.z * d##i.z + d##i.w * d##i.w; }
        FORN8(EPI_N)
#undef EPI_N
        ss0 += __shfl_xor_sync(0xFFFFFFFFu, ss0, 1);
        ss0 += __shfl_xor_sync(0xFFFFFFFFu, ss0, 2);
        ss1 += __shfl_xor_sync(0xFFFFFFFFu, ss1, 1);
        ss1 += __shfl_xor_sync(0xFFFFFFFFu, ss1, 2);
        float inv0 = 1.0f / fmaxf(sqrtf(ss0), 1e-12f);
        float inv1 = 1.0f / fmaxf(sqrtf(ss1), 1e-12f);
#define EPI_NS(i) {                                                            \
        if (grow0 < nrows)                                                     \
            *(float2*)(outp + (size_t)grow0 * 64 + (i) * 8 + q * 2) =          \
                make_float2(d##i.x * inv0, d##i.y * inv0);                     \
        if (grow1 < nrows)                                                     \
            *(float2*)(outp + (size_t)grow1 * 64 + (i) * 8 + q * 2) =          \
                make_float2(d##i.z * inv1, d##i.w * inv1); }
        FORN8(EPI_NS)
#undef EPI_NS
    }
}

__global__ void __launch_bounds__(128) k_pre(
    const float* __restrict__ hb, const float* __restrict__ hz,
    const float* __restrict__ W1, int n_brand, int n_size)
{
    __shared__ float rowv[128];
    const int t = threadIdx.x;
    const int r = blockIdx.x;
    const float* src;
    const float* W;
    float* dst;
    if (r < n_brand) {
        src = hb + (size_t)r * 128; W = W1 + (size_t)128 * 128; dst = g_brand_part + (size_t)r * 128;
    } else {
        int rr = r - n_brand;
        src = hz + (size_t)rr * 128; W = W1 + (size_t)256 * 128; dst = g_size_part + (size_t)rr * 128;
    }
    rowv[t] = src[t];
    __syncthreads();
    float a = 0.0f;
#pragma unroll 4
    for (int k = 0; k < 128; k++) a = fmaf(rowv[k], W[(size_t)k * 128 + t], a);
    dst[t] = a;
}

__global__ void k_rowstart(const int* __restrict__ seg, int E, int n_users)
{
    int e = blockIdx.x * blockDim.x + threadIdx.x;
    if (e >= E) return;
    int s = seg[e];
    int p = (e == 0) ? -1 : seg[e - 1];
    for (int u = p + 1; u <= s; ++u) g_row_start[u] = e;
    if (e == E - 1) {
        for (int u = s + 1; u <= n_users; ++u) g_row_start[u] = E;
    }
}

__global__ void k_hist(const float* __restrict__ item_vec,
                       const int* __restrict__ items, int n_users)
{
    int gw   = (blockIdx.x * blockDim.x + threadIdx.x) >> 5;
    int lane = threadIdx.x & 31;
    if (gw >= n_users) return;
    int s = g_row_start[gw], e = g_row_start[gw + 1];
    float a0 = 0.0f, a1 = 0.0f;
    if (e > s) {
        int it = items[s];
        for (int j = s; j < e; ++j) {
            int nx = (j + 1 < e) ? items[j + 1] : 0;
            const float* p = item_vec + (size_t)it * 64;
            a0 += p[lane];
            a1 += p[32 + lane];
            it = nx;
        }
        float inv = 1.0f / (float)(e - s);
        a0 *= inv; a1 *= inv;
    }
    g_hist_pool[(size_t)gw * 64 + lane]      = a0;
    g_hist_pool[(size_t)gw * 64 + 32 + lane] = a1;
}

extern "C" void kernel_launch(void* const* d_in, const int* in_sizes, int n_in,
                              void* d_out, int out_size)
{
    const float* h_user   = (const float*)d_in[0];
    const float* h_tire   = (const float*)d_in[1];
    const float* h_brand  = (const float*)d_in[2];
    const float* h_size   = (const float*)d_in[3];
    const float* specs    = (const float*)d_in[4];
    const float* text_emb = (const float*)d_in[5];
    const int*   bidx     = (const int*)d_in[6];
    const int*   sidx     = (const int*)d_in[7];
    const int*   hitems   = (const int*)d_in[8];
    const int*   hseg     = (const int*)d_in[9];
    const float* W_tp = (const float*)d_in[10]; const float* b_tp = (const float*)d_in[11];
    const float* W_i1 = (const float*)d_in[12]; const float* b_i1 = (const float*)d_in[13];
    const float* W_i2 = (const float*)d_in[14]; const float* b_i2 = (const float*)d_in[15];
    const float* W_i3 = (const float*)d_in[16]; const float* b_i3 = (const float*)d_in[17];
    const float* W_u1 = (const float*)d_in[18]; const float* b_u1 = (const float*)d_in[19];
    const float* W_u2 = (const float*)d_in[20]; const float* b_u2 = (const float*)d_in[21];
    const float* W_u3 = (const float*)d_in[22]; const float* b_u3 = (const float*)d_in[23];

    const int n_users = in_sizes[0] / 128;
    const int n_tires = in_sizes[1] / 128;
    const int n_brand = in_sizes[2] / 128;
    const int n_size  = in_sizes[3] / 128;
    const int E       = in_sizes[8];

    float* out      = (float*)d_out;
    float* user_vec = out;
    float* item_vec = out + (size_t)n_users * 64;

    const int nbT = (n_tires + 63) / 64;
    const int nbU = (n_users + 63) / 64;

    cudaFuncSetAttribute(k_text, cudaFuncAttributeMaxDynamicSharedMemorySize, SM_TEXT);
    cudaFuncSetAttribute(k_tower<256>, cudaFuncAttributeMaxDynamicSharedMemorySize, SM_TOWER);
    cudaFuncSetAttribute(k_tower<192>, cudaFuncAttributeMaxDynamicSharedMemorySize, SM_TOWER);

    k_wsplit<<<(384 * 64  + 255) / 256, 256>>>(W_tp, WB_TP, 384, 64,  0);
    k_wsplit<<<(256 * 128 + 255) / 256, 256>>>(W_i1, WB_I1, 256, 128, 1);
    k_wsplit<<<(128 * 128 + 255) / 256, 256>>>(W_i2, WB_I2, 128, 128, 0);
    k_wsplit<<<(128 * 64  + 255) / 256, 256>>>(W_i3, WB_I3, 128, 64,  0);
    k_wsplit<<<(192 * 128 + 255) / 256, 256>>>(W_u1, WB_U1, 192, 128, 0);
    k_wsplit<<<(128 * 128 + 255) / 256, 256>>>(W_u2, WB_U2, 128, 128, 0);
    k_wsplit<<<(128 * 64  + 255) / 256, 256>>>(W_u3, WB_U3, 128, 64,  0);

    k_pre<<<n_brand + n_size, 128>>>(h_brand, h_size, W_i1, n_brand, n_size);

    k_text<<<nbT, 128, SM_TEXT>>>(text_emb, b_tp, n_tires);

    k_tower<256><<<nbT, 128, SM_TOWER>>>(
        h_tire, 128, 2, specs, 1,
        WB_I1, b_i1, 1, bidx, sidx,
        WB_I2, b_i2, WB_I3, b_i3,
        item_vec, n_tires);

    k_rowstart<<<(E + 255) / 256, 256>>>(hseg, E, n_users);
    k_hist<<<((size_t)n_users * 32 + 255) / 256, 256>>>(item_vec, hitems, n_users);

    k_tower<192><<<nbU, 128, SM_TOWER>>>(
        h_user, 128, 2, nullptr, 0,
        WB_U1, b_u1, 0, nullptr, nullptr,
        WB_U2, b_u2, WB_U3, b_u3,
        user_vec, n_users);
}